// round 8
// baseline (speedup 1.0000x reference)
#include <cuda_runtime.h>
#include <cuda_bf16.h>
#include <stdint.h>

#define NN 100000
#define EE 3200000
#define IN_CH 512

// Scratch (device globals — no allocation allowed)
__device__ float  g_deg[NN];
__device__ float  g_dinv[NN];
__device__ float4 g_h[NN];     // h_pre after GEMM, then h2 (relu'd) after relu kernel
__device__ float4 g_agg1[NN];
__device__ float4 g_agg2[NN];
__device__ int2   g_edge[EE];  // packed (src, dst) int32
__device__ int    g_is64;      // 1 if edge_index is int64, 0 if int32

// ---------------------------------------------------------------------------
// K0: detect edge_index dtype. If the buffer is int64, every sampled value
// lies in [0, NN). If it is int32, the int64 interpretation fuses adjacent
// indices -> huge values, caught within 64 samples (false-pos prob ~1e-320).
__global__ void k_detect(const void* __restrict__ ei) {
    if (threadIdx.x == 0 && blockIdx.x == 0) {
        const long long* p = (const long long*)ei;
        int ok = 1;
        for (int i = 0; i < 64; i++) {
            long long v = p[i];
            if (v < 0 || v >= NN) { ok = 0; break; }
        }
        g_is64 = ok;
    }
}

// K1: deg init (self-loop contributes 1)
__global__ void k_deg_init(int n) {
    int i = blockIdx.x * blockDim.x + threadIdx.x;
    if (i < n) g_deg[i] = 1.0f;
}

// K2: preprocess — narrow edge_index to packed int2, count indegree
__global__ void k_pre(const void* __restrict__ ei, int E, int n) {
    int e = blockIdx.x * blockDim.x + threadIdx.x;
    if (e >= E) return;
    int s, d;
    if (g_is64) {
        const long long* p = (const long long*)ei;
        s = (int)p[e];
        d = (int)p[(size_t)E + e];
    } else {
        const int* p = (const int*)ei;
        s = p[e];
        d = p[E + e];
    }
    // defensive clamp: wrong dtype guess -> wrong answer (diagnosable), not a crash
    if ((unsigned)s >= (unsigned)n) s = 0;
    if ((unsigned)d >= (unsigned)n) d = 0;
    g_edge[e] = make_int2(s, d);
    atomicAdd(&g_deg[d], 1.0f);
}

// K3: h_pre = x @ W1  (warp per node), fused: dinv = rsqrt(deg),
//     agg1 self-loop init = h_pre * dinv^2
__global__ void k_gemm(const float* __restrict__ x, const float* __restrict__ W1, int n) {
    __shared__ float4 sW[IN_CH];   // W1 row k -> float4 of 4 output channels
    int tid = threadIdx.x;
    const float4* W4 = (const float4*)W1;
    for (int i = tid; i < IN_CH; i += blockDim.x) sW[i] = W4[i];
    __syncthreads();

    int warp = tid >> 5, lane = tid & 31;
    int node = blockIdx.x * (blockDim.x >> 5) + warp;
    if (node >= n) return;

    const float4* xr = (const float4*)(x + (size_t)node * IN_CH);
    float4 acc = make_float4(0.f, 0.f, 0.f, 0.f);
#pragma unroll
    for (int j = 0; j < 4; j++) {
        int idx = j * 32 + lane;          // float4 index within row [0,128)
        float4 xv = xr[idx];
        int k = idx * 4;
        float4 w0 = sW[k], w1 = sW[k + 1], w2 = sW[k + 2], w3 = sW[k + 3];
        acc.x += xv.x * w0.x + xv.y * w1.x + xv.z * w2.x + xv.w * w3.x;
        acc.y += xv.x * w0.y + xv.y * w1.y + xv.z * w2.y + xv.w * w3.y;
        acc.z += xv.x * w0.z + xv.y * w1.z + xv.z * w2.z + xv.w * w3.z;
        acc.w += xv.x * w0.w + xv.y * w1.w + xv.z * w2.w + xv.w * w3.w;
    }
#pragma unroll
    for (int off = 16; off; off >>= 1) {
        acc.x += __shfl_xor_sync(0xFFFFFFFFu, acc.x, off);
        acc.y += __shfl_xor_sync(0xFFFFFFFFu, acc.y, off);
        acc.z += __shfl_xor_sync(0xFFFFFFFFu, acc.z, off);
        acc.w += __shfl_xor_sync(0xFFFFFFFFu, acc.w, off);
    }
    if (lane == 0) {
        g_h[node] = acc;
        float di = rsqrtf(g_deg[node]);
        g_dinv[node] = di;
        float s = di * di;                 // self-loop norm
        g_agg1[node] = make_float4(acc.x * s, acc.y * s, acc.z * s, acc.w * s);
    }
}

// K4: agg1[dst] += h_pre[src] * dinv[src]*dinv[dst]  (vector reduction)
__global__ void k_agg1(int E) {
    int e = blockIdx.x * blockDim.x + threadIdx.x;
    if (e >= E) return;
    int2 sd = g_edge[e];
    float w = g_dinv[sd.x] * g_dinv[sd.y];
    float4 v = g_h[sd.x];
    atomicAdd(&g_agg1[sd.y], make_float4(v.x * w, v.y * w, v.z * w, v.w * w));
}

// K5: h2 = relu(agg1 + b1); agg2 self-loop init = h2 * dinv^2
__global__ void k_relu(const float* __restrict__ b1, int n) {
    int i = blockIdx.x * blockDim.x + threadIdx.x;
    if (i >= n) return;
    float b0 = b1[0], bb1 = b1[1], b2 = b1[2], b3 = b1[3];
    float4 a = g_agg1[i];
    float4 h;
    h.x = fmaxf(a.x + b0, 0.f);
    h.y = fmaxf(a.y + bb1, 0.f);
    h.z = fmaxf(a.z + b2, 0.f);
    h.w = fmaxf(a.w + b3, 0.f);
    g_h[i] = h;                             // reuse g_h for h2
    float di = g_dinv[i];
    float s = di * di;
    g_agg2[i] = make_float4(h.x * s, h.y * s, h.z * s, h.w * s);
}

// K6: agg2[dst] += h2[src] * w
__global__ void k_agg2(int E) {
    int e = blockIdx.x * blockDim.x + threadIdx.x;
    if (e >= E) return;
    int2 sd = g_edge[e];
    float w = g_dinv[sd.x] * g_dinv[sd.y];
    float4 v = g_h[sd.x];
    atomicAdd(&g_agg2[sd.y], make_float4(v.x * w, v.y * w, v.z * w, v.w * w));
}

// K7: mu = agg2 @ W_mu + b_mu ; logstd = agg2 @ W_ls + b_ls
//     out layout: [mu (N*2 floats) | logstd (N*2 floats)]
__global__ void k_final(const float* __restrict__ Wmu, const float* __restrict__ bmu,
                        const float* __restrict__ Wls, const float* __restrict__ bls,
                        float* __restrict__ out, int n) {
    int i = blockIdx.x * blockDim.x + threadIdx.x;
    if (i >= n) return;
    float4 a = g_agg2[i];
    // W is [4,2] row-major: W[c*2 + o]
    float m0 = a.x * Wmu[0] + a.y * Wmu[2] + a.z * Wmu[4] + a.w * Wmu[6] + bmu[0];
    float m1 = a.x * Wmu[1] + a.y * Wmu[3] + a.z * Wmu[5] + a.w * Wmu[7] + bmu[1];
    float l0 = a.x * Wls[0] + a.y * Wls[2] + a.z * Wls[4] + a.w * Wls[6] + bls[0];
    float l1 = a.x * Wls[1] + a.y * Wls[3] + a.z * Wls[5] + a.w * Wls[7] + bls[1];
    ((float2*)out)[i] = make_float2(m0, m1);
    ((float2*)(out + 2 * (size_t)n))[i] = make_float2(l0, l1);
}

extern "C" void kernel_launch(void* const* d_in, const int* in_sizes, int n_in,
                              void* d_out, int out_size) {
    const float* x   = (const float*)d_in[0];
    const void*  ei  = d_in[1];
    const float* W1  = (const float*)d_in[2];
    const float* b1  = (const float*)d_in[3];
    const float* Wmu = (const float*)d_in[4];
    const float* bmu = (const float*)d_in[5];
    const float* Wls = (const float*)d_in[6];
    const float* bls = (const float*)d_in[7];
    float* out = (float*)d_out;

    int n = in_sizes[0] / IN_CH;     // 100000
    int E = in_sizes[1] / 2;         // 3200000

    int nb_n = (n + 255) / 256;
    int nb_e = (E + 255) / 256;
    int nb_g = (n + 7) / 8;          // 8 warps (nodes) per 256-thread block

    k_detect<<<1, 32>>>(ei);
    k_deg_init<<<nb_n, 256>>>(n);
    k_pre<<<nb_e, 256>>>(ei, E, n);
    k_gemm<<<nb_g, 256>>>(x, W1, n);
    k_agg1<<<nb_e, 256>>>(E);
    k_relu<<<nb_n, 256>>>(b1, n);
    k_agg2<<<nb_e, 256>>>(E);
    k_final<<<nb_n, 256>>>(Wmu, bmu, Wls, bls, out, n);
}

// round 11
// speedup vs baseline: 1.6224x; 1.6224x over previous
#include <cuda_runtime.h>
#include <cuda_bf16.h>
#include <stdint.h>

#define NN 100000
#define EE 3200000
#define IN_CH 512

// Scratch (device globals — no allocation allowed)
__device__ float  g_deg[NN];
__device__ float  g_dinv[NN];
__device__ float4 g_h[NN];     // hs = h_pre*dinv after GEMM, then h2s = h2*dinv after relu
__device__ float4 g_agg1[NN];  // pre-multiplied sum: dinv[d] applied in k_relu
__device__ float4 g_agg2[NN];  // pre-multiplied sum: dinv[d] applied in k_final
__device__ int2   g_edge[EE];  // packed (src, dst) int32
__device__ int    g_is64;      // 1 if edge_index is int64, 0 if int32

// ---------------------------------------------------------------------------
// K1: deg init (self-loop contributes 1). Block 0 warp 0 also detects the
// edge_index dtype: int64 data -> all 32 sampled values in [0, NN); int32
// data -> fused pairs give huge values (false-pos prob ~(1e-5)^32).
__global__ void k_deg_init(const void* __restrict__ ei, int n) {
    if (blockIdx.x == 0 && threadIdx.x < 32) {
        const long long* p = (const long long*)ei;
        long long v = p[threadIdx.x];
        int ok = (v >= 0 && v < NN);
        unsigned m = __ballot_sync(0xFFFFFFFFu, ok);
        if (threadIdx.x == 0) g_is64 = (m == 0xFFFFFFFFu) ? 1 : 0;
    }
    int i = blockIdx.x * blockDim.x + threadIdx.x;
    if (i < n) g_deg[i] = 1.0f;
}

// K2: preprocess — narrow edge_index to packed int2, count indegree
__global__ void k_pre(const void* __restrict__ ei, int E, int n) {
    int e = blockIdx.x * blockDim.x + threadIdx.x;
    if (e >= E) return;
    int s, d;
    if (g_is64) {
        const long long* p = (const long long*)ei;
        s = (int)p[e];
        d = (int)p[(size_t)E + e];
    } else {
        const int* p = (const int*)ei;
        s = p[e];
        d = p[E + e];
    }
    // defensive clamp: wrong dtype guess -> wrong answer (diagnosable), not a crash
    if ((unsigned)s >= (unsigned)n) s = 0;
    if ((unsigned)d >= (unsigned)n) d = 0;
    g_edge[e] = make_int2(s, d);
    atomicAdd(&g_deg[d], 1.0f);
}

// K3: h_pre = x @ W1  (warp per node), W TRANSPOSED in smem for conflict-free
//     LDS.128. Fused: dinv = rsqrt(deg); store hs = h_pre*dinv; init
//     agg1 = hs (self-loop term of the pre-multiplied sum).
__global__ void k_gemm(const float* __restrict__ x, const float* __restrict__ W1, int n) {
    __shared__ float sWT[4][IN_CH];   // sWT[o][k] = W1[k*4 + o]
    int tid = threadIdx.x;
    for (int i = tid; i < IN_CH * 4; i += blockDim.x) {
        int k = i >> 2, o = i & 3;
        sWT[o][k] = W1[i];
    }
    __syncthreads();

    int warp = tid >> 5, lane = tid & 31;
    int node = blockIdx.x * (blockDim.x >> 5) + warp;
    if (node >= n) return;

    const float4* xr = (const float4*)(x + (size_t)node * IN_CH);
    const float4* w0p = (const float4*)sWT[0];
    const float4* w1p = (const float4*)sWT[1];
    const float4* w2p = (const float4*)sWT[2];
    const float4* w3p = (const float4*)sWT[3];

    float4 acc = make_float4(0.f, 0.f, 0.f, 0.f);
#pragma unroll
    for (int j = 0; j < 4; j++) {
        int idx = j * 32 + lane;          // float4 index within row [0,128)
        float4 xv = xr[idx];
        float4 w0 = w0p[idx], w1 = w1p[idx], w2 = w2p[idx], w3 = w3p[idx];
        acc.x += xv.x * w0.x + xv.y * w0.y + xv.z * w0.z + xv.w * w0.w;
        acc.y += xv.x * w1.x + xv.y * w1.y + xv.z * w1.z + xv.w * w1.w;
        acc.z += xv.x * w2.x + xv.y * w2.y + xv.z * w2.z + xv.w * w2.w;
        acc.w += xv.x * w3.x + xv.y * w3.y + xv.z * w3.z + xv.w * w3.w;
    }
#pragma unroll
    for (int off = 16; off; off >>= 1) {
        acc.x += __shfl_xor_sync(0xFFFFFFFFu, acc.x, off);
        acc.y += __shfl_xor_sync(0xFFFFFFFFu, acc.y, off);
        acc.z += __shfl_xor_sync(0xFFFFFFFFu, acc.z, off);
        acc.w += __shfl_xor_sync(0xFFFFFFFFu, acc.w, off);
    }
    if (lane == 0) {
        float di = rsqrtf(g_deg[node]);
        g_dinv[node] = di;
        float4 hs = make_float4(acc.x * di, acc.y * di, acc.z * di, acc.w * di);
        g_h[node] = hs;
        g_agg1[node] = hs;               // self-loop term (pre-multiplied sum)
    }
}

// K4: agg1[dst] += hs[src]   (pure vector reduction — norm factored out)
__global__ void k_agg1(int E) {
    int e = blockIdx.x * blockDim.x + threadIdx.x;
    if (e >= E) return;
    int2 sd = g_edge[e];
    atomicAdd(&g_agg1[sd.y], g_h[sd.x]);
}

// K5: h2 = relu(dinv*agg1 + b1); store h2s = h2*dinv; init agg2 = h2s
__global__ void k_relu(const float* __restrict__ b1, int n) {
    int i = blockIdx.x * blockDim.x + threadIdx.x;
    if (i >= n) return;
    float b0 = b1[0], bb1 = b1[1], b2 = b1[2], b3 = b1[3];
    float di = g_dinv[i];
    float4 a = g_agg1[i];
    float4 h;
    h.x = fmaxf(di * a.x + b0, 0.f);
    h.y = fmaxf(di * a.y + bb1, 0.f);
    h.z = fmaxf(di * a.z + b2, 0.f);
    h.w = fmaxf(di * a.w + b3, 0.f);
    float4 h2s = make_float4(h.x * di, h.y * di, h.z * di, h.w * di);
    g_h[i] = h2s;                        // reuse g_h for h2s
    g_agg2[i] = h2s;                     // self-loop term
}

// K6: agg2[dst] += h2s[src]
__global__ void k_agg2(int E) {
    int e = blockIdx.x * blockDim.x + threadIdx.x;
    if (e >= E) return;
    int2 sd = g_edge[e];
    atomicAdd(&g_agg2[sd.y], g_h[sd.x]);
}

// K7: a = dinv*agg2; mu = a @ W_mu + b_mu ; logstd = a @ W_ls + b_ls
//     out layout: [mu (N*2 floats) | logstd (N*2 floats)]
__global__ void k_final(const float* __restrict__ Wmu, const float* __restrict__ bmu,
                        const float* __restrict__ Wls, const float* __restrict__ bls,
                        float* __restrict__ out, int n) {
    int i = blockIdx.x * blockDim.x + threadIdx.x;
    if (i >= n) return;
    float di = g_dinv[i];
    float4 r = g_agg2[i];
    float4 a = make_float4(r.x * di, r.y * di, r.z * di, r.w * di);
    // W is [4,2] row-major: W[c*2 + o]
    float m0 = a.x * Wmu[0] + a.y * Wmu[2] + a.z * Wmu[4] + a.w * Wmu[6] + bmu[0];
    float m1 = a.x * Wmu[1] + a.y * Wmu[3] + a.z * Wmu[5] + a.w * Wmu[7] + bmu[1];
    float l0 = a.x * Wls[0] + a.y * Wls[2] + a.z * Wls[4] + a.w * Wls[6] + bls[0];
    float l1 = a.x * Wls[1] + a.y * Wls[3] + a.z * Wls[5] + a.w * Wls[7] + bls[1];
    ((float2*)out)[i] = make_float2(m0, m1);
    ((float2*)(out + 2 * (size_t)n))[i] = make_float2(l0, l1);
}

extern "C" void kernel_launch(void* const* d_in, const int* in_sizes, int n_in,
                              void* d_out, int out_size) {
    const float* x   = (const float*)d_in[0];
    const void*  ei  = d_in[1];
    const float* W1  = (const float*)d_in[2];
    const float* b1  = (const float*)d_in[3];
    const float* Wmu = (const float*)d_in[4];
    const float* bmu = (const float*)d_in[5];
    const float* Wls = (const float*)d_in[6];
    const float* bls = (const float*)d_in[7];
    float* out = (float*)d_out;

    int n = in_sizes[0] / IN_CH;     // 100000
    int E = in_sizes[1] / 2;         // 3200000

    int nb_n = (n + 255) / 256;
    int nb_e = (E + 255) / 256;
    int nb_g = (n + 7) / 8;          // 8 warps (nodes) per 256-thread block

    k_deg_init<<<nb_n, 256>>>(ei, n);
    k_pre<<<nb_e, 256>>>(ei, E, n);
    k_gemm<<<nb_g, 256>>>(x, W1, n);
    k_agg1<<<nb_e, 256>>>(E);
    k_relu<<<nb_n, 256>>>(b1, n);
    k_agg2<<<nb_e, 256>>>(E);
    k_final<<<nb_n, 256>>>(Wmu, bmu, Wls, bls, out, n);
}